// round 9
// baseline (speedup 1.0000x reference)
#include <cuda_runtime.h>
#include <math.h>

#define N_NODES   50000
#define N_EDGES   800000
#define E_TOT     (N_EDGES + N_NODES)   // 850000 (with self loops)
#define N_GRAPHS  64
#define HID       128
#define HEADS     4
#define CH        32
#define N_CLASSES 10
#define N_LAYERS  3
#define NEG_SLOPE 0.2f

// ---------------- scratch (module-load allocated, allowed) ----------------
__device__ __align__(16) float g_xl[N_NODES * HID];
__device__ __align__(16) float g_xr[N_NODES * HID];
__device__ __align__(16) float g_h [N_NODES * HID];
__device__ int   g_deg   [N_NODES];
__device__ int   g_incl  [N_NODES];
__device__ int   g_rowptr[N_NODES + 1];
__device__ int   g_cursor[N_NODES];
__device__ int   g_srcs  [E_TOT];
__device__ int   g_bsums[64];
__device__ int   g_boffs[64];
__device__ int   g_is64;
__device__ __align__(16) float g_pool[N_GRAPHS * HID];
__device__ float g_cnt [N_GRAPHS];

// dtype-robust index load (edge_index / batch may be int32 or int64)
__device__ __forceinline__ int load_idx(const void* p, long i, int is64) {
    if (is64) return (int)((const long long*)p)[i];
    return ((const int*)p)[i];
}

// ---------------- dtype detection -----------------------------------------
__global__ void k_detect(const void* __restrict__ ei) {
    if (threadIdx.x == 0 && blockIdx.x == 0) {
        const long long* p = (const long long*)ei;
        int ok = 1;
        for (int i = 0; i < 256; i++) {
            long long v = p[i];
            if (v < 0 || v >= N_NODES) { ok = 0; break; }
        }
        g_is64 = ok;
    }
}

// ---------------- CSR build (dst is layer-invariant; built once/launch) ---
__global__ void k_zero_deg() {
    int i = blockIdx.x * blockDim.x + threadIdx.x;
    if (i < N_NODES) g_deg[i] = 0;
}

__global__ void k_count(const void* __restrict__ ei) {
    int i = blockIdx.x * blockDim.x + threadIdx.x;
    int is64 = g_is64;
    if (i < E_TOT) {
        int dst = (i < N_EDGES) ? load_idx(ei, (long)N_EDGES + i, is64)
                                : (i - N_EDGES);
        if (dst >= 0 && dst < N_NODES) atomicAdd(&g_deg[dst], 1);
    }
}

__global__ void k_scan_block() {   // 49 blocks x 1024, Hillis-Steele
    __shared__ int s[1024];
    int i = blockIdx.x * 1024 + threadIdx.x;
    int v = (i < N_NODES) ? g_deg[i] : 0;
    s[threadIdx.x] = v;
    __syncthreads();
    for (int off = 1; off < 1024; off <<= 1) {
        int t = 0;
        if (threadIdx.x >= off) t = s[threadIdx.x - off];
        __syncthreads();
        if (threadIdx.x >= off) s[threadIdx.x] += t;
        __syncthreads();
    }
    if (i < N_NODES) g_incl[i] = s[threadIdx.x];
    if (threadIdx.x == 1023) g_bsums[blockIdx.x] = s[1023];
}

__global__ void k_scan_sums(int nb) {
    if (blockIdx.x == 0 && threadIdx.x == 0) {
        int acc = 0;
        for (int b = 0; b < nb; b++) { g_boffs[b] = acc; acc += g_bsums[b]; }
    }
}

__global__ void k_scan_final() {
    int i = blockIdx.x * blockDim.x + threadIdx.x;
    if (i < N_NODES) {
        int rp = g_incl[i] - g_deg[i] + g_boffs[i >> 10];
        g_rowptr[i] = rp;
        g_cursor[i] = rp;
    }
    if (i == 0) g_rowptr[N_NODES] = E_TOT;
}

__global__ void k_scatter(const void* __restrict__ ei) {
    int i = blockIdx.x * blockDim.x + threadIdx.x;
    int is64 = g_is64;
    if (i < E_TOT) {
        int src, dst;
        if (i < N_EDGES) {
            src = load_idx(ei, i, is64);
            dst = load_idx(ei, (long)N_EDGES + i, is64);
        } else {
            src = dst = i - N_EDGES;
        }
        if (src >= 0 && src < N_NODES && dst >= 0 && dst < N_NODES) {
            int pos = atomicAdd(&g_cursor[dst], 1);
            g_srcs[pos] = src;
        }
    }
}

// ------- fused dual GEMM: xl = hin@Wl + bl, xr = hin@Wr + br --------------
// 64-row x 256-col (128 xl + 128 xr) tile per block, 256 threads,
// 8x8 accumulators per thread. use_x != 0 -> input is x_in (layer 0).
__global__ __launch_bounds__(256)
void k_gemm2(const float* __restrict__ x_in, int use_x,
             const float* __restrict__ Wl, const float* __restrict__ Wr,
             const float* __restrict__ bl, const float* __restrict__ br) {
    const float* __restrict__ hin = use_x ? x_in : g_h;

    __shared__ float As[16][65];
    __shared__ __align__(16) float Ws[16][256];   // [.][0:128)=Wl, [128:256)=Wr
    int row0 = blockIdx.x * 64;
    int tid = threadIdx.x;
    int tx = tid & 31, ty = tid >> 5;   // tx: 4-col group, ty: 8-row group

    float accl[8][4], accr[8][4];
#pragma unroll
    for (int r = 0; r < 8; r++)
#pragma unroll
        for (int c = 0; c < 4; c++) { accl[r][c] = 0.f; accr[r][c] = 0.f; }

    for (int kc = 0; kc < 128; kc += 16) {
#pragma unroll
        for (int i = 0; i < 4; i++) {
            int idx = tid + i * 256;
            int kk = idx & 15, r = idx >> 4;
            int row = row0 + r;
            As[kk][r] = (row < N_NODES) ? hin[row * 128 + kc + kk] : 0.f;
        }
#pragma unroll
        for (int i = 0; i < 4; i++) {
            int f4 = tid + i * 256;           // 0..1023 float4 slots
            int kk = f4 >> 6, nn4 = f4 & 63;  // 64 float4 per 256-col row
            float4 v;
            if (nn4 < 32) v = *(const float4*)&Wl[(kc + kk) * 128 + nn4 * 4];
            else          v = *(const float4*)&Wr[(kc + kk) * 128 + (nn4 - 32) * 4];
            *(float4*)&Ws[kk][nn4 * 4] = v;
        }
        __syncthreads();
#pragma unroll
        for (int k = 0; k < 16; k++) {
            float4 wl = *(const float4*)&Ws[k][tx * 4];
            float4 wr = *(const float4*)&Ws[k][128 + tx * 4];
#pragma unroll
            for (int r = 0; r < 8; r++) {
                float a = As[k][ty * 8 + r];   // broadcast within warp
                accl[r][0] += a * wl.x; accl[r][1] += a * wl.y;
                accl[r][2] += a * wl.z; accl[r][3] += a * wl.w;
                accr[r][0] += a * wr.x; accr[r][1] += a * wr.y;
                accr[r][2] += a * wr.z; accr[r][3] += a * wr.w;
            }
        }
        __syncthreads();
    }
    float4 bbl = *(const float4*)&bl[tx * 4];
    float4 bbr = *(const float4*)&br[tx * 4];
#pragma unroll
    for (int r = 0; r < 8; r++) {
        int row = row0 + ty * 8 + r;
        if (row < N_NODES) {
            float4 o;
            o.x = accl[r][0] + bbl.x; o.y = accl[r][1] + bbl.y;
            o.z = accl[r][2] + bbl.z; o.w = accl[r][3] + bbl.w;
            *(float4*)&g_xl[row * 128 + tx * 4] = o;
            o.x = accr[r][0] + bbr.x; o.y = accr[r][1] + bbr.y;
            o.z = accr[r][2] + bbr.z; o.w = accr[r][3] + bbr.w;
            *(float4*)&g_xr[row * 128 + tx * 4] = o;
        }
    }
}

// ------- fused GATv2 edge phase: one warp per dst, ONLINE softmax ---------
// lane -> (head h = lane>>3, channels (lane&7)*4 .. +3). Single sweep over
// the neighbor list: running max with rescaling (flash-attention style).
__global__ __launch_bounds__(256)
void k_attn(const float* __restrict__ att_l, const float* __restrict__ bias_l) {
    int warp = (blockIdx.x * blockDim.x + threadIdx.x) >> 5;
    if (warp >= N_NODES) return;
    int lane = threadIdx.x & 31;
    int d = warp;
    int off = (lane >> 3) * 32 + (lane & 7) * 4;

    float4 xr4 = *(const float4*)&g_xr[d * 128 + off];
    float4 a4  = *(const float4*)&att_l[off];
    int beg = g_rowptr[d], end = g_rowptr[d + 1];

    float m = -1e30f, denom = 0.f;
    float ax = 0.f, ay = 0.f, az = 0.f, aw = 0.f;
    for (int j = beg; j < end; j++) {
        int s = g_srcs[j];
        float4 xs = __ldg((const float4*)&g_xl[s * 128 + off]);
        float t0 = xs.x + xr4.x; t0 = t0 > 0.f ? t0 : NEG_SLOPE * t0;
        float t1 = xs.y + xr4.y; t1 = t1 > 0.f ? t1 : NEG_SLOPE * t1;
        float t2 = xs.z + xr4.z; t2 = t2 > 0.f ? t2 : NEG_SLOPE * t2;
        float t3 = xs.w + xr4.w; t3 = t3 > 0.f ? t3 : NEG_SLOPE * t3;
        float p = a4.x * t0 + a4.y * t1 + a4.z * t2 + a4.w * t3;
        p += __shfl_xor_sync(0xffffffffu, p, 1);
        p += __shfl_xor_sync(0xffffffffu, p, 2);
        p += __shfl_xor_sync(0xffffffffu, p, 4);   // all 8 lanes of head hold e
        float nm = fmaxf(m, p);
        float scale = __expf(m - nm);   // m=-1e30 first iter -> 0, harmless
        float ee = __expf(p - nm);
        denom = denom * scale + ee;
        ax = ax * scale + ee * xs.x;
        ay = ay * scale + ee * xs.y;
        az = az * scale + ee * xs.z;
        aw = aw * scale + ee * xs.w;
        m = nm;
    }
    float inv = 1.f / denom;
    float4 bb = *(const float4*)&bias_l[off];
    float o0 = ax * inv + bb.x; o0 = o0 > 0.f ? o0 : expm1f(o0);
    float o1 = ay * inv + bb.y; o1 = o1 > 0.f ? o1 : expm1f(o1);
    float o2 = az * inv + bb.z; o2 = o2 > 0.f ? o2 : expm1f(o2);
    float o3 = aw * inv + bb.w; o3 = o3 > 0.f ? o3 : expm1f(o3);
    float4 o; o.x = o0; o.y = o1; o.z = o2; o.w = o3;
    *(float4*)&g_h[d * 128 + off] = o;
}

// ---------------- pooling + classifier head -------------------------------
__global__ void k_zero_pool() {
    int i = blockIdx.x * blockDim.x + threadIdx.x;
    if (i < N_GRAPHS * HID) g_pool[i] = 0.f;
    if (i < N_GRAPHS) g_cnt[i] = 0.f;
}

__global__ void k_pool(const void* __restrict__ batch) {
    int idx = blockIdx.x * blockDim.x + threadIdx.x;
    int is64 = g_is64;
    if (idx < N_NODES * HID) {
        int n = idx >> 7, c = idx & 127;
        int b = load_idx(batch, n, is64);
        if (b >= 0 && b < N_GRAPHS) {
            atomicAdd(&g_pool[b * 128 + c], g_h[idx]);
            if (c == 0) atomicAdd(&g_cnt[b], 1.f);
        }
    }
}

__global__ void k_final(const float* __restrict__ lin_w,
                        const float* __restrict__ lin_b,
                        float* __restrict__ out) {
    int g = blockIdx.x;
    int lane = threadIdx.x;          // 32 threads/block
    float z = -1e30f, zv = 0.f;
    if (lane < N_CLASSES) {
        float invc = 1.f / fmaxf(g_cnt[g], 1.f);
        float acc = lin_b[lane];
        for (int k = 0; k < 128; k++)
            acc += g_pool[g * 128 + k] * invc * lin_w[k * N_CLASSES + lane];
        acc = acc > 0.f ? acc : expm1f(acc);   // elu
        zv = acc; z = acc;
    }
    float zm = z;
    for (int o = 16; o; o >>= 1) zm = fmaxf(zm, __shfl_xor_sync(0xffffffffu, zm, o));
    float ez = (lane < N_CLASSES) ? __expf(zv - zm) : 0.f;
    float se = ez;
    for (int o = 16; o; o >>= 1) se += __shfl_xor_sync(0xffffffffu, se, o);
    if (lane < N_CLASSES) out[g * N_CLASSES + lane] = zv - zm - logf(se);
}

// ---------------- launcher: kernel launches ONLY --------------------------
extern "C" void kernel_launch(void* const* d_in, const int* in_sizes, int n_in,
                              void* d_out, int out_size) {
    (void)in_sizes; (void)n_in; (void)out_size;
    const float* x     = (const float*)d_in[0];
    const void*  ei    = d_in[1];
    const void*  batch = d_in[2];
    const float* Wl    = (const float*)d_in[3];
    const float* Wr    = (const float*)d_in[4];
    const float* bl    = (const float*)d_in[5];
    const float* br    = (const float*)d_in[6];
    const float* att   = (const float*)d_in[7];
    const float* bias  = (const float*)d_in[8];
    const float* lin_w = (const float*)d_in[9];
    const float* lin_b = (const float*)d_in[10];
    float* out = (float*)d_out;

    // index dtype detection + CSR by destination (layer-invariant)
    k_detect    <<<1, 32>>>(ei);
    k_zero_deg  <<<(N_NODES + 255) / 256, 256>>>();
    k_count     <<<(E_TOT   + 255) / 256, 256>>>(ei);
    int nb = (N_NODES + 1023) / 1024;
    k_scan_block<<<nb, 1024>>>();
    k_scan_sums <<<1, 1>>>(nb);
    k_scan_final<<<(N_NODES + 255) / 256, 256>>>();
    k_scatter   <<<(E_TOT   + 255) / 256, 256>>>(ei);

    const int gemm_grid = (N_NODES + 63) / 64;
    const int attn_grid = (N_NODES * 32 + 255) / 256;
    for (int l = 0; l < N_LAYERS; l++) {
        int use_x = (l == 0) ? 1 : 0;
        k_gemm2<<<gemm_grid, 256>>>(x, use_x,
                                    Wl + l * 128 * 128, Wr + l * 128 * 128,
                                    bl + l * 128, br + l * 128);
        k_attn<<<attn_grid, 256>>>(att + l * 128, bias + l * 128);
    }

    k_zero_pool<<<(N_GRAPHS * HID + 255) / 256, 256>>>();
    k_pool     <<<(N_NODES * HID + 255) / 256, 256>>>(batch);
    k_final    <<<N_GRAPHS, 32>>>(lin_w, lin_b, out);
}

// round 13
// speedup vs baseline: 1.4599x; 1.4599x over previous
#include <cuda_runtime.h>
#include <math.h>
#include <stdint.h>

#define N_NODES   50000
#define N_EDGES   800000
#define E_TOT     (N_EDGES + N_NODES)   // 850000 (with self loops)
#define N_GRAPHS  64
#define HID       128
#define HEADS     4
#define CH        32
#define N_CLASSES 10
#define N_LAYERS  3
#define NEG_SLOPE 0.2f

// ---------------- scratch (module-load allocated, allowed) ----------------
__device__ __align__(16) float g_xl[N_NODES * HID];
__device__ __align__(16) float g_xr[N_NODES * HID];
__device__ __align__(16) float g_h [N_NODES * HID];
__device__ __align__(16) float g_e [E_TOT * HEADS];
__device__ int   g_deg   [N_NODES];
__device__ int   g_incl  [N_NODES];
__device__ int   g_rowptr[N_NODES + 1];
__device__ int   g_cursor[N_NODES];
__device__ int   g_srcs  [E_TOT];
__device__ int   g_bsums[64];
__device__ int   g_boffs[64];
__device__ int   g_is64;
__device__ __align__(16) float g_pool[N_GRAPHS * HID];
__device__ float g_cnt [N_GRAPHS];

// dtype-robust index load (edge_index / batch may be int32 or int64)
__device__ __forceinline__ int load_idx(const void* p, long i, int is64) {
    if (is64) return (int)((const long long*)p)[i];
    return ((const int*)p)[i];
}

// ---------------- dtype detection -----------------------------------------
__global__ void k_detect(const void* __restrict__ ei) {
    if (threadIdx.x == 0 && blockIdx.x == 0) {
        const long long* p = (const long long*)ei;
        int ok = 1;
        for (int i = 0; i < 256; i++) {
            long long v = p[i];
            if (v < 0 || v >= N_NODES) { ok = 0; break; }
        }
        g_is64 = ok;
    }
}

// ---------------- CSR build (dst is layer-invariant; built once/launch) ---
__global__ void k_zero_deg() {
    int i = blockIdx.x * blockDim.x + threadIdx.x;
    if (i < N_NODES) g_deg[i] = 0;
}

__global__ void k_count(const void* __restrict__ ei) {
    int i = blockIdx.x * blockDim.x + threadIdx.x;
    int is64 = g_is64;
    if (i < E_TOT) {
        int dst = (i < N_EDGES) ? load_idx(ei, (long)N_EDGES + i, is64)
                                : (i - N_EDGES);
        if (dst >= 0 && dst < N_NODES) atomicAdd(&g_deg[dst], 1);
    }
}

__global__ void k_scan_block() {   // 49 blocks x 1024, Hillis-Steele
    __shared__ int s[1024];
    int i = blockIdx.x * 1024 + threadIdx.x;
    int v = (i < N_NODES) ? g_deg[i] : 0;
    s[threadIdx.x] = v;
    __syncthreads();
    for (int off = 1; off < 1024; off <<= 1) {
        int t = 0;
        if (threadIdx.x >= off) t = s[threadIdx.x - off];
        __syncthreads();
        if (threadIdx.x >= off) s[threadIdx.x] += t;
        __syncthreads();
    }
    if (i < N_NODES) g_incl[i] = s[threadIdx.x];
    if (threadIdx.x == 1023) g_bsums[blockIdx.x] = s[1023];
}

__global__ void k_scan_sums(int nb) {
    if (blockIdx.x == 0 && threadIdx.x == 0) {
        int acc = 0;
        for (int b = 0; b < nb; b++) { g_boffs[b] = acc; acc += g_bsums[b]; }
    }
}

__global__ void k_scan_final() {
    int i = blockIdx.x * blockDim.x + threadIdx.x;
    if (i < N_NODES) {
        int rp = g_incl[i] - g_deg[i] + g_boffs[i >> 10];
        g_rowptr[i] = rp;
        g_cursor[i] = rp;
    }
    if (i == 0) g_rowptr[N_NODES] = E_TOT;
}

__global__ void k_scatter(const void* __restrict__ ei) {
    int i = blockIdx.x * blockDim.x + threadIdx.x;
    int is64 = g_is64;
    if (i < E_TOT) {
        int src, dst;
        if (i < N_EDGES) {
            src = load_idx(ei, i, is64);
            dst = load_idx(ei, (long)N_EDGES + i, is64);
        } else {
            src = dst = i - N_EDGES;
        }
        if (src >= 0 && src < N_NODES && dst >= 0 && dst < N_NODES) {
            int pos = atomicAdd(&g_cursor[dst], 1);
            g_srcs[pos] = src;
        }
    }
}

// ---------------- TF32 split helper + MMA ---------------------------------
__device__ __forceinline__ void split_tf32(float v, uint32_t& hi, uint32_t& lo) {
    uint32_t h;
    asm("cvt.rna.tf32.f32 %0, %1;" : "=r"(h) : "f"(v));
    float r = v - __uint_as_float(h);
    uint32_t l;
    asm("cvt.rna.tf32.f32 %0, %1;" : "=r"(l) : "f"(r));
    hi = h; lo = l;
}

#define MMA_TF32(c, a, b0, b1)                                              \
    asm volatile(                                                           \
        "mma.sync.aligned.m16n8k8.row.col.f32.tf32.tf32.f32 "               \
        "{%0,%1,%2,%3}, {%4,%5,%6,%7}, {%8,%9}, {%0,%1,%2,%3};"             \
        : "+f"((c)[0]), "+f"((c)[1]), "+f"((c)[2]), "+f"((c)[3])            \
        : "r"((a)[0]), "r"((a)[1]), "r"((a)[2]), "r"((a)[3]),               \
          "r"(b0), "r"(b1))

// ------- GEMM (tensor core, 3xTF32): out[64r x 128c] = hin @ W + b --------
// 256 thr = 8 warps (2x4). Warp tile 32x32 = 2 m-tiles x 4 n-tiles m16n8k8.
// use_x != 0 -> input x_in (layer 0), else g_h.  out_sel: 0->g_xl, 1->g_xr.
__global__ __launch_bounds__(256)
void k_gemm_tc(const float* __restrict__ x_in, int use_x,
               const float* __restrict__ W,
               const float* __restrict__ b, int out_sel) {
    const float* __restrict__ hin = use_x ? x_in : g_h;
    float* __restrict__ out = out_sel ? g_xr : g_xl;

    __shared__ float As_hi[64][20], As_lo[64][20];     // 64 rows x 16 k
    __shared__ float Ws_hi[16][136], Ws_lo[16][136];   // 16 k x 128 n

    int tid  = threadIdx.x;
    int lane = tid & 31, wid = tid >> 5;
    int g = lane >> 2, t = lane & 3;
    int wm = wid >> 2, wn = wid & 3;
    int row0 = blockIdx.x * 64;

    float acc[2][4][4];
#pragma unroll
    for (int mt = 0; mt < 2; mt++)
#pragma unroll
        for (int nt = 0; nt < 4; nt++)
#pragma unroll
            for (int i = 0; i < 4; i++) acc[mt][nt][i] = 0.f;

    for (int kc = 0; kc < 128; kc += 16) {
        // stage A 64x16 (1 float4 per thread)
        {
            int row = tid >> 2, k4 = (tid & 3) * 4;
            int grow = row0 + row;
            float4 v = make_float4(0.f, 0.f, 0.f, 0.f);
            if (grow < N_NODES) v = *(const float4*)&hin[grow * 128 + kc + k4];
            uint32_t h0, l0, h1, l1, h2, l2, h3, l3;
            split_tf32(v.x, h0, l0); split_tf32(v.y, h1, l1);
            split_tf32(v.z, h2, l2); split_tf32(v.w, h3, l3);
            float4 hh, ll;
            hh.x = __uint_as_float(h0); hh.y = __uint_as_float(h1);
            hh.z = __uint_as_float(h2); hh.w = __uint_as_float(h3);
            ll.x = __uint_as_float(l0); ll.y = __uint_as_float(l1);
            ll.z = __uint_as_float(l2); ll.w = __uint_as_float(l3);
            *(float4*)&As_hi[row][k4] = hh;
            *(float4*)&As_lo[row][k4] = ll;
        }
        // stage W 16x128 (2 float4 per thread)
#pragma unroll
        for (int j = 0; j < 2; j++) {
            int f4 = tid + j * 256;
            int k = f4 >> 5, n4 = (f4 & 31) * 4;
            float4 v = *(const float4*)&W[(kc + k) * 128 + n4];
            uint32_t h0, l0, h1, l1, h2, l2, h3, l3;
            split_tf32(v.x, h0, l0); split_tf32(v.y, h1, l1);
            split_tf32(v.z, h2, l2); split_tf32(v.w, h3, l3);
            float4 hh, ll;
            hh.x = __uint_as_float(h0); hh.y = __uint_as_float(h1);
            hh.z = __uint_as_float(h2); hh.w = __uint_as_float(h3);
            ll.x = __uint_as_float(l0); ll.y = __uint_as_float(l1);
            ll.z = __uint_as_float(l2); ll.w = __uint_as_float(l3);
            *(float4*)&Ws_hi[k][n4] = hh;
            *(float4*)&Ws_lo[k][n4] = ll;
        }
        __syncthreads();

#pragma unroll
        for (int ks = 0; ks < 2; ks++) {
            int k0 = ks * 8;
            uint32_t ah[2][4], al[2][4];
#pragma unroll
            for (int mt = 0; mt < 2; mt++) {
                int rb = wm * 32 + mt * 16;
                ah[mt][0] = __float_as_uint(As_hi[rb + g    ][k0 + t    ]);
                ah[mt][1] = __float_as_uint(As_hi[rb + g + 8][k0 + t    ]);
                ah[mt][2] = __float_as_uint(As_hi[rb + g    ][k0 + t + 4]);
                ah[mt][3] = __float_as_uint(As_hi[rb + g + 8][k0 + t + 4]);
                al[mt][0] = __float_as_uint(As_lo[rb + g    ][k0 + t    ]);
                al[mt][1] = __float_as_uint(As_lo[rb + g + 8][k0 + t    ]);
                al[mt][2] = __float_as_uint(As_lo[rb + g    ][k0 + t + 4]);
                al[mt][3] = __float_as_uint(As_lo[rb + g + 8][k0 + t + 4]);
            }
#pragma unroll
            for (int nt = 0; nt < 4; nt++) {
                int col = wn * 32 + nt * 8 + g;
                uint32_t bh0 = __float_as_uint(Ws_hi[k0 + t    ][col]);
                uint32_t bh1 = __float_as_uint(Ws_hi[k0 + t + 4][col]);
                uint32_t bl0 = __float_as_uint(Ws_lo[k0 + t    ][col]);
                uint32_t bl1 = __float_as_uint(Ws_lo[k0 + t + 4][col]);
#pragma unroll
                for (int mt = 0; mt < 2; mt++) {
                    MMA_TF32(acc[mt][nt], ah[mt], bh0, bh1);
                    MMA_TF32(acc[mt][nt], ah[mt], bl0, bl1);
                    MMA_TF32(acc[mt][nt], al[mt], bh0, bh1);
                }
            }
        }
        __syncthreads();
    }

    // epilogue: c0,c1 -> row g, cols 2t,2t+1 ; c2,c3 -> row g+8
#pragma unroll
    for (int mt = 0; mt < 2; mt++) {
        int r0 = row0 + wm * 32 + mt * 16 + g;
        int r1 = r0 + 8;
#pragma unroll
        for (int nt = 0; nt < 4; nt++) {
            int c = wn * 32 + nt * 8 + 2 * t;
            float2 bb = *(const float2*)&b[c];
            if (r0 < N_NODES) {
                float2 o; o.x = acc[mt][nt][0] + bb.x; o.y = acc[mt][nt][1] + bb.y;
                *(float2*)&out[r0 * 128 + c] = o;
            }
            if (r1 < N_NODES) {
                float2 o; o.x = acc[mt][nt][2] + bb.x; o.y = acc[mt][nt][3] + bb.y;
                *(float2*)&out[r1 * 128 + c] = o;
            }
        }
    }
}

// ------- fused GATv2 edge phase: one warp per destination node ------------
// (identical to the 700us R8 version: two passes, score buffer g_e)
__global__ __launch_bounds__(256)
void k_attn(const float* __restrict__ att_l, const float* __restrict__ bias_l) {
    int warp = (blockIdx.x * blockDim.x + threadIdx.x) >> 5;
    if (warp >= N_NODES) return;
    int lane = threadIdx.x & 31;
    int d = warp;
    int h = lane >> 3;
    int off = h * 32 + (lane & 7) * 4;

    float4 xr4 = *(const float4*)&g_xr[d * 128 + off];
    float4 a4  = *(const float4*)&att_l[off];
    int beg = g_rowptr[d], end = g_rowptr[d + 1];

    // pass 1: edge scores + per-head running max
    float m = -1e30f;
    for (int j = beg; j < end; j++) {
        int s = g_srcs[j];
        float4 xs = *(const float4*)&g_xl[s * 128 + off];
        float t0 = xs.x + xr4.x; t0 = t0 > 0.f ? t0 : NEG_SLOPE * t0;
        float t1 = xs.y + xr4.y; t1 = t1 > 0.f ? t1 : NEG_SLOPE * t1;
        float t2 = xs.z + xr4.z; t2 = t2 > 0.f ? t2 : NEG_SLOPE * t2;
        float t3 = xs.w + xr4.w; t3 = t3 > 0.f ? t3 : NEG_SLOPE * t3;
        float p = a4.x * t0 + a4.y * t1 + a4.z * t2 + a4.w * t3;
        p += __shfl_xor_sync(0xffffffffu, p, 1);
        p += __shfl_xor_sync(0xffffffffu, p, 2);
        p += __shfl_xor_sync(0xffffffffu, p, 4);   // all 8 lanes of head hold e
        if ((lane & 7) == 0) g_e[j * 4 + h] = p;
        m = fmaxf(m, p);
    }

    // pass 2: exp, denominator, weighted aggregate (no atomics)
    float denom = 0.f;
    float ax = 0.f, ay = 0.f, az = 0.f, aw = 0.f;
    for (int j = beg; j < end; j++) {
        int s = g_srcs[j];
        float ee = __expf(g_e[j * 4 + h] - m);
        denom += ee;
        float4 xs = *(const float4*)&g_xl[s * 128 + off];
        ax += ee * xs.x; ay += ee * xs.y; az += ee * xs.z; aw += ee * xs.w;
    }
    float inv = 1.f / denom;
    float4 bb = *(const float4*)&bias_l[off];
    float o0 = ax * inv + bb.x; o0 = o0 > 0.f ? o0 : expm1f(o0);
    float o1 = ay * inv + bb.y; o1 = o1 > 0.f ? o1 : expm1f(o1);
    float o2 = az * inv + bb.z; o2 = o2 > 0.f ? o2 : expm1f(o2);
    float o3 = aw * inv + bb.w; o3 = o3 > 0.f ? o3 : expm1f(o3);
    float4 o; o.x = o0; o.y = o1; o.z = o2; o.w = o3;
    *(float4*)&g_h[d * 128 + off] = o;
}

// ---------------- pooling + classifier head -------------------------------
__global__ void k_zero_pool() {
    int i = blockIdx.x * blockDim.x + threadIdx.x;
    if (i < N_GRAPHS * HID) g_pool[i] = 0.f;
    if (i < N_GRAPHS) g_cnt[i] = 0.f;
}

__global__ void k_pool(const void* __restrict__ batch) {
    int idx = blockIdx.x * blockDim.x + threadIdx.x;
    int is64 = g_is64;
    if (idx < N_NODES * HID) {
        int n = idx >> 7, c = idx & 127;
        int b = load_idx(batch, n, is64);
        if (b >= 0 && b < N_GRAPHS) {
            atomicAdd(&g_pool[b * 128 + c], g_h[idx]);
            if (c == 0) atomicAdd(&g_cnt[b], 1.f);
        }
    }
}

__global__ void k_final(const float* __restrict__ lin_w,
                        const float* __restrict__ lin_b,
                        float* __restrict__ out) {
    int g = blockIdx.x;
    int lane = threadIdx.x;          // 32 threads/block
    float z = -1e30f, zv = 0.f;
    if (lane < N_CLASSES) {
        float invc = 1.f / fmaxf(g_cnt[g], 1.f);
        float acc = lin_b[lane];
        for (int k = 0; k < 128; k++)
            acc += g_pool[g * 128 + k] * invc * lin_w[k * N_CLASSES + lane];
        acc = acc > 0.f ? acc : expm1f(acc);   // elu
        zv = acc; z = acc;
    }
    float zm = z;
    for (int o = 16; o; o >>= 1) zm = fmaxf(zm, __shfl_xor_sync(0xffffffffu, zm, o));
    float ez = (lane < N_CLASSES) ? __expf(zv - zm) : 0.f;
    float se = ez;
    for (int o = 16; o; o >>= 1) se += __shfl_xor_sync(0xffffffffu, se, o);
    if (lane < N_CLASSES) out[g * N_CLASSES + lane] = zv - zm - logf(se);
}

// ---------------- launcher: kernel launches ONLY --------------------------
extern "C" void kernel_launch(void* const* d_in, const int* in_sizes, int n_in,
                              void* d_out, int out_size) {
    (void)in_sizes; (void)n_in; (void)out_size;
    const float* x     = (const float*)d_in[0];
    const void*  ei    = d_in[1];
    const void*  batch = d_in[2];
    const float* Wl    = (const float*)d_in[3];
    const float* Wr    = (const float*)d_in[4];
    const float* bl    = (const float*)d_in[5];
    const float* br    = (const float*)d_in[6];
    const float* att   = (const float*)d_in[7];
    const float* bias  = (const float*)d_in[8];
    const float* lin_w = (const float*)d_in[9];
    const float* lin_b = (const float*)d_in[10];
    float* out = (float*)d_out;

    // index dtype detection + CSR by destination (layer-invariant)
    k_detect    <<<1, 32>>>(ei);
    k_zero_deg  <<<(N_NODES + 255) / 256, 256>>>();
    k_count     <<<(E_TOT   + 255) / 256, 256>>>(ei);
    int nb = (N_NODES + 1023) / 1024;
    k_scan_block<<<nb, 1024>>>();
    k_scan_sums <<<1, 1>>>(nb);
    k_scan_final<<<(N_NODES + 255) / 256, 256>>>();
    k_scatter   <<<(E_TOT   + 255) / 256, 256>>>(ei);

    const int gemm_grid = (N_NODES + 63) / 64;
    const int attn_grid = (N_NODES * 32 + 255) / 256;
    for (int l = 0; l < N_LAYERS; l++) {
        int use_x = (l == 0) ? 1 : 0;
        k_gemm_tc<<<gemm_grid, 256>>>(x, use_x, Wl + l * 128 * 128, bl + l * 128, 0);
        k_gemm_tc<<<gemm_grid, 256>>>(x, use_x, Wr + l * 128 * 128, br + l * 128, 1);
        k_attn<<<attn_grid, 256>>>(att + l * 128, bias + l * 128);
    }

    k_zero_pool<<<(N_GRAPHS * HID + 255) / 256, 256>>>();
    k_pool     <<<(N_NODES * HID + 255) / 256, 256>>>(batch);
    k_final    <<<N_GRAPHS, 32>>>(lin_w, lin_b, out);
}

// round 14
// speedup vs baseline: 1.6000x; 1.0959x over previous
#include <cuda_runtime.h>
#include <math.h>
#include <stdint.h>

#define N_NODES   50000
#define N_EDGES   800000
#define E_TOT     (N_EDGES + N_NODES)   // 850000 (with self loops)
#define N_GRAPHS  64
#define HID       128
#define HEADS     4
#define CH        32
#define N_CLASSES 10
#define N_LAYERS  3
#define NEG_SLOPE 0.2f

// ---------------- scratch (module-load allocated, allowed) ----------------
__device__ __align__(16) float g_xl[N_NODES * HID];
__device__ __align__(16) float g_xr[N_NODES * HID];
__device__ __align__(16) float g_h [N_NODES * HID];
__device__ int   g_deg   [N_NODES];
__device__ int   g_incl  [N_NODES];
__device__ int   g_rowptr[N_NODES + 1];
__device__ int   g_cursor[N_NODES];
__device__ int   g_srcs  [E_TOT];
__device__ int   g_bsums[64];
__device__ int   g_boffs[64];
__device__ int   g_is64;
__device__ __align__(16) float g_pool[N_GRAPHS * HID];
__device__ float g_cnt [N_GRAPHS];

// dtype-robust index load (edge_index / batch may be int32 or int64)
__device__ __forceinline__ int load_idx(const void* p, long i, int is64) {
    if (is64) return (int)((const long long*)p)[i];
    return ((const int*)p)[i];
}

// ---------------- dtype detection -----------------------------------------
__global__ void k_detect(const void* __restrict__ ei) {
    if (threadIdx.x == 0 && blockIdx.x == 0) {
        const long long* p = (const long long*)ei;
        int ok = 1;
        for (int i = 0; i < 256; i++) {
            long long v = p[i];
            if (v < 0 || v >= N_NODES) { ok = 0; break; }
        }
        g_is64 = ok;
    }
}

// ---------------- CSR build (dst is layer-invariant; built once/launch) ---
__global__ void k_zero_deg() {
    int i = blockIdx.x * blockDim.x + threadIdx.x;
    if (i < N_NODES) g_deg[i] = 0;
}

__global__ void k_count(const void* __restrict__ ei) {
    int i = blockIdx.x * blockDim.x + threadIdx.x;
    int is64 = g_is64;
    if (i < E_TOT) {
        int dst = (i < N_EDGES) ? load_idx(ei, (long)N_EDGES + i, is64)
                                : (i - N_EDGES);
        if (dst >= 0 && dst < N_NODES) atomicAdd(&g_deg[dst], 1);
    }
}

__global__ void k_scan_block() {   // 49 blocks x 1024, Hillis-Steele
    __shared__ int s[1024];
    int i = blockIdx.x * 1024 + threadIdx.x;
    int v = (i < N_NODES) ? g_deg[i] : 0;
    s[threadIdx.x] = v;
    __syncthreads();
    for (int off = 1; off < 1024; off <<= 1) {
        int t = 0;
        if (threadIdx.x >= off) t = s[threadIdx.x - off];
        __syncthreads();
        if (threadIdx.x >= off) s[threadIdx.x] += t;
        __syncthreads();
    }
    if (i < N_NODES) g_incl[i] = s[threadIdx.x];
    if (threadIdx.x == 1023) g_bsums[blockIdx.x] = s[1023];
}

__global__ void k_scan_sums(int nb) {
    if (blockIdx.x == 0 && threadIdx.x == 0) {
        int acc = 0;
        for (int b = 0; b < nb; b++) { g_boffs[b] = acc; acc += g_bsums[b]; }
    }
}

__global__ void k_scan_final() {
    int i = blockIdx.x * blockDim.x + threadIdx.x;
    if (i < N_NODES) {
        int rp = g_incl[i] - g_deg[i] + g_boffs[i >> 10];
        g_rowptr[i] = rp;
        g_cursor[i] = rp;
    }
    if (i == 0) g_rowptr[N_NODES] = E_TOT;
}

__global__ void k_scatter(const void* __restrict__ ei) {
    int i = blockIdx.x * blockDim.x + threadIdx.x;
    int is64 = g_is64;
    if (i < E_TOT) {
        int src, dst;
        if (i < N_EDGES) {
            src = load_idx(ei, i, is64);
            dst = load_idx(ei, (long)N_EDGES + i, is64);
        } else {
            src = dst = i - N_EDGES;
        }
        if (src >= 0 && src < N_NODES && dst >= 0 && dst < N_NODES) {
            int pos = atomicAdd(&g_cursor[dst], 1);
            g_srcs[pos] = src;
        }
    }
}

// ---------------- TF32 split helper + MMA ---------------------------------
__device__ __forceinline__ void split_tf32(float v, uint32_t& hi, uint32_t& lo) {
    uint32_t h;
    asm("cvt.rna.tf32.f32 %0, %1;" : "=r"(h) : "f"(v));
    float r = v - __uint_as_float(h);
    uint32_t l;
    asm("cvt.rna.tf32.f32 %0, %1;" : "=r"(l) : "f"(r));
    hi = h; lo = l;
}

#define MMA_TF32(c, a, b0, b1)                                              \
    asm volatile(                                                           \
        "mma.sync.aligned.m16n8k8.row.col.f32.tf32.tf32.f32 "               \
        "{%0,%1,%2,%3}, {%4,%5,%6,%7}, {%8,%9}, {%0,%1,%2,%3};"             \
        : "+f"((c)[0]), "+f"((c)[1]), "+f"((c)[2]), "+f"((c)[3])            \
        : "r"((a)[0]), "r"((a)[1]), "r"((a)[2]), "r"((a)[3]),               \
          "r"(b0), "r"(b1))

// ------- GEMM (tensor core, 3xTF32): out[64r x 128c] = hin @ W + b --------
// 256 thr = 8 warps (2x4). Warp tile 32x32 = 2 m-tiles x 4 n-tiles m16n8k8.
// use_x != 0 -> input x_in (layer 0), else g_h.  out_sel: 0->g_xl, 1->g_xr.
__global__ __launch_bounds__(256)
void k_gemm_tc(const float* __restrict__ x_in, int use_x,
               const float* __restrict__ W,
               const float* __restrict__ b, int out_sel) {
    const float* __restrict__ hin = use_x ? x_in : g_h;
    float* __restrict__ out = out_sel ? g_xr : g_xl;

    __shared__ float As_hi[64][20], As_lo[64][20];     // 64 rows x 16 k
    __shared__ float Ws_hi[16][136], Ws_lo[16][136];   // 16 k x 128 n

    int tid  = threadIdx.x;
    int lane = tid & 31, wid = tid >> 5;
    int g = lane >> 2, t = lane & 3;
    int wm = wid >> 2, wn = wid & 3;
    int row0 = blockIdx.x * 64;

    float acc[2][4][4];
#pragma unroll
    for (int mt = 0; mt < 2; mt++)
#pragma unroll
        for (int nt = 0; nt < 4; nt++)
#pragma unroll
            for (int i = 0; i < 4; i++) acc[mt][nt][i] = 0.f;

    for (int kc = 0; kc < 128; kc += 16) {
        // stage A 64x16 (1 float4 per thread)
        {
            int row = tid >> 2, k4 = (tid & 3) * 4;
            int grow = row0 + row;
            float4 v = make_float4(0.f, 0.f, 0.f, 0.f);
            if (grow < N_NODES) v = *(const float4*)&hin[grow * 128 + kc + k4];
            uint32_t h0, l0, h1, l1, h2, l2, h3, l3;
            split_tf32(v.x, h0, l0); split_tf32(v.y, h1, l1);
            split_tf32(v.z, h2, l2); split_tf32(v.w, h3, l3);
            float4 hh, ll;
            hh.x = __uint_as_float(h0); hh.y = __uint_as_float(h1);
            hh.z = __uint_as_float(h2); hh.w = __uint_as_float(h3);
            ll.x = __uint_as_float(l0); ll.y = __uint_as_float(l1);
            ll.z = __uint_as_float(l2); ll.w = __uint_as_float(l3);
            *(float4*)&As_hi[row][k4] = hh;
            *(float4*)&As_lo[row][k4] = ll;
        }
        // stage W 16x128 (2 float4 per thread)
#pragma unroll
        for (int j = 0; j < 2; j++) {
            int f4 = tid + j * 256;
            int k = f4 >> 5, n4 = (f4 & 31) * 4;
            float4 v = *(const float4*)&W[(kc + k) * 128 + n4];
            uint32_t h0, l0, h1, l1, h2, l2, h3, l3;
            split_tf32(v.x, h0, l0); split_tf32(v.y, h1, l1);
            split_tf32(v.z, h2, l2); split_tf32(v.w, h3, l3);
            float4 hh, ll;
            hh.x = __uint_as_float(h0); hh.y = __uint_as_float(h1);
            hh.z = __uint_as_float(h2); hh.w = __uint_as_float(h3);
            ll.x = __uint_as_float(l0); ll.y = __uint_as_float(l1);
            ll.z = __uint_as_float(l2); ll.w = __uint_as_float(l3);
            *(float4*)&Ws_hi[k][n4] = hh;
            *(float4*)&Ws_lo[k][n4] = ll;
        }
        __syncthreads();

#pragma unroll
        for (int ks = 0; ks < 2; ks++) {
            int k0 = ks * 8;
            uint32_t ah[2][4], al[2][4];
#pragma unroll
            for (int mt = 0; mt < 2; mt++) {
                int rb = wm * 32 + mt * 16;
                ah[mt][0] = __float_as_uint(As_hi[rb + g    ][k0 + t    ]);
                ah[mt][1] = __float_as_uint(As_hi[rb + g + 8][k0 + t    ]);
                ah[mt][2] = __float_as_uint(As_hi[rb + g    ][k0 + t + 4]);
                ah[mt][3] = __float_as_uint(As_hi[rb + g + 8][k0 + t + 4]);
                al[mt][0] = __float_as_uint(As_lo[rb + g    ][k0 + t    ]);
                al[mt][1] = __float_as_uint(As_lo[rb + g + 8][k0 + t    ]);
                al[mt][2] = __float_as_uint(As_lo[rb + g    ][k0 + t + 4]);
                al[mt][3] = __float_as_uint(As_lo[rb + g + 8][k0 + t + 4]);
            }
#pragma unroll
            for (int nt = 0; nt < 4; nt++) {
                int col = wn * 32 + nt * 8 + g;
                uint32_t bh0 = __float_as_uint(Ws_hi[k0 + t    ][col]);
                uint32_t bh1 = __float_as_uint(Ws_hi[k0 + t + 4][col]);
                uint32_t bl0 = __float_as_uint(Ws_lo[k0 + t    ][col]);
                uint32_t bl1 = __float_as_uint(Ws_lo[k0 + t + 4][col]);
#pragma unroll
                for (int mt = 0; mt < 2; mt++) {
                    MMA_TF32(acc[mt][nt], ah[mt], bh0, bh1);
                    MMA_TF32(acc[mt][nt], ah[mt], bl0, bl1);
                    MMA_TF32(acc[mt][nt], al[mt], bh0, bh1);
                }
            }
        }
        __syncthreads();
    }

    // epilogue: c0,c1 -> row g, cols 2t,2t+1 ; c2,c3 -> row g+8
#pragma unroll
    for (int mt = 0; mt < 2; mt++) {
        int r0 = row0 + wm * 32 + mt * 16 + g;
        int r1 = r0 + 8;
#pragma unroll
        for (int nt = 0; nt < 4; nt++) {
            int c = wn * 32 + nt * 8 + 2 * t;
            float2 bb = *(const float2*)&b[c];
            if (r0 < N_NODES) {
                float2 o; o.x = acc[mt][nt][0] + bb.x; o.y = acc[mt][nt][1] + bb.y;
                *(float2*)&out[r0 * 128 + c] = o;
            }
            if (r1 < N_NODES) {
                float2 o; o.x = acc[mt][nt][2] + bb.x; o.y = acc[mt][nt][3] + bb.y;
                *(float2*)&out[r1 * 128 + c] = o;
            }
        }
    }
}

// ------- fused GATv2 edge phase: one warp per dst, ONLINE softmax ---------
// Single sweep over the neighbor list (flash-attention style rescaling).
// 2-way unrolled so consecutive xl-row loads are in flight together.
__global__ __launch_bounds__(256)
void k_attn(const float* __restrict__ att_l, const float* __restrict__ bias_l) {
    int warp = (blockIdx.x * blockDim.x + threadIdx.x) >> 5;
    if (warp >= N_NODES) return;
    int lane = threadIdx.x & 31;
    int d = warp;
    int off = (lane >> 3) * 32 + (lane & 7) * 4;

    float4 xr4 = *(const float4*)&g_xr[d * 128 + off];
    float4 a4  = *(const float4*)&att_l[off];
    int beg = g_rowptr[d], end = g_rowptr[d + 1];

    float m = -1e30f, denom = 0.f;
    float ax = 0.f, ay = 0.f, az = 0.f, aw = 0.f;

    int j = beg;
    for (; j + 1 < end; j += 2) {
        int s0 = g_srcs[j], s1 = g_srcs[j + 1];
        float4 x0 = __ldg((const float4*)&g_xl[s0 * 128 + off]);
        float4 x1 = __ldg((const float4*)&g_xl[s1 * 128 + off]);

        float t0 = x0.x + xr4.x; t0 = t0 > 0.f ? t0 : NEG_SLOPE * t0;
        float t1 = x0.y + xr4.y; t1 = t1 > 0.f ? t1 : NEG_SLOPE * t1;
        float t2 = x0.z + xr4.z; t2 = t2 > 0.f ? t2 : NEG_SLOPE * t2;
        float t3 = x0.w + xr4.w; t3 = t3 > 0.f ? t3 : NEG_SLOPE * t3;
        float p0 = a4.x * t0 + a4.y * t1 + a4.z * t2 + a4.w * t3;
        p0 += __shfl_xor_sync(0xffffffffu, p0, 1);
        p0 += __shfl_xor_sync(0xffffffffu, p0, 2);
        p0 += __shfl_xor_sync(0xffffffffu, p0, 4);

        float u0 = x1.x + xr4.x; u0 = u0 > 0.f ? u0 : NEG_SLOPE * u0;
        float u1 = x1.y + xr4.y; u1 = u1 > 0.f ? u1 : NEG_SLOPE * u1;
        float u2 = x1.z + xr4.z; u2 = u2 > 0.f ? u2 : NEG_SLOPE * u2;
        float u3 = x1.w + xr4.w; u3 = u3 > 0.f ? u3 : NEG_SLOPE * u3;
        float p1 = a4.x * u0 + a4.y * u1 + a4.z * u2 + a4.w * u3;
        p1 += __shfl_xor_sync(0xffffffffu, p1, 1);
        p1 += __shfl_xor_sync(0xffffffffu, p1, 2);
        p1 += __shfl_xor_sync(0xffffffffu, p1, 4);

        // joint rescale for the pair
        float pm = fmaxf(p0, p1);
        float nm = fmaxf(m, pm);
        float scale = __expf(m - nm);
        float e0 = __expf(p0 - nm);
        float e1 = __expf(p1 - nm);
        denom = denom * scale + e0 + e1;
        ax = ax * scale + e0 * x0.x + e1 * x1.x;
        ay = ay * scale + e0 * x0.y + e1 * x1.y;
        az = az * scale + e0 * x0.z + e1 * x1.z;
        aw = aw * scale + e0 * x0.w + e1 * x1.w;
        m = nm;
    }
    if (j < end) {
        int s = g_srcs[j];
        float4 xs = __ldg((const float4*)&g_xl[s * 128 + off]);
        float t0 = xs.x + xr4.x; t0 = t0 > 0.f ? t0 : NEG_SLOPE * t0;
        float t1 = xs.y + xr4.y; t1 = t1 > 0.f ? t1 : NEG_SLOPE * t1;
        float t2 = xs.z + xr4.z; t2 = t2 > 0.f ? t2 : NEG_SLOPE * t2;
        float t3 = xs.w + xr4.w; t3 = t3 > 0.f ? t3 : NEG_SLOPE * t3;
        float p = a4.x * t0 + a4.y * t1 + a4.z * t2 + a4.w * t3;
        p += __shfl_xor_sync(0xffffffffu, p, 1);
        p += __shfl_xor_sync(0xffffffffu, p, 2);
        p += __shfl_xor_sync(0xffffffffu, p, 4);
        float nm = fmaxf(m, p);
        float scale = __expf(m - nm);
        float ee = __expf(p - nm);
        denom = denom * scale + ee;
        ax = ax * scale + ee * xs.x;
        ay = ay * scale + ee * xs.y;
        az = az * scale + ee * xs.z;
        aw = aw * scale + ee * xs.w;
        m = nm;
    }

    float inv = 1.f / denom;
    float4 bb = *(const float4*)&bias_l[off];
    float o0 = ax * inv + bb.x; o0 = o0 > 0.f ? o0 : expm1f(o0);
    float o1 = ay * inv + bb.y; o1 = o1 > 0.f ? o1 : expm1f(o1);
    float o2 = az * inv + bb.z; o2 = o2 > 0.f ? o2 : expm1f(o2);
    float o3 = aw * inv + bb.w; o3 = o3 > 0.f ? o3 : expm1f(o3);
    float4 o; o.x = o0; o.y = o1; o.z = o2; o.w = o3;
    *(float4*)&g_h[d * 128 + off] = o;
}

// ---------------- pooling + classifier head -------------------------------
__global__ void k_zero_pool() {
    int i = blockIdx.x * blockDim.x + threadIdx.x;
    if (i < N_GRAPHS * HID) g_pool[i] = 0.f;
    if (i < N_GRAPHS) g_cnt[i] = 0.f;
}

__global__ void k_pool(const void* __restrict__ batch) {
    int idx = blockIdx.x * blockDim.x + threadIdx.x;
    int is64 = g_is64;
    if (idx < N_NODES * HID) {
        int n = idx >> 7, c = idx & 127;
        int b = load_idx(batch, n, is64);
        if (b >= 0 && b < N_GRAPHS) {
            atomicAdd(&g_pool[b * 128 + c], g_h[idx]);
            if (c == 0) atomicAdd(&g_cnt[b], 1.f);
        }
    }
}

__global__ void k_final(const float* __restrict__ lin_w,
                        const float* __restrict__ lin_b,
                        float* __restrict__ out) {
    int g = blockIdx.x;
    int lane = threadIdx.x;          // 32 threads/block
    float z = -1e30f, zv = 0.f;
    if (lane < N_CLASSES) {
        float invc = 1.f / fmaxf(g_cnt[g], 1.f);
        float acc = lin_b[lane];
        for (int k = 0; k < 128; k++)
            acc += g_pool[g * 128 + k] * invc * lin_w[k * N_CLASSES + lane];
        acc = acc > 0.f ? acc : expm1f(acc);   // elu
        zv = acc; z = acc;
    }
    float zm = z;
    for (int o = 16; o; o >>= 1) zm = fmaxf(zm, __shfl_xor_sync(0xffffffffu, zm, o));
    float ez = (lane < N_CLASSES) ? __expf(zv - zm) : 0.f;
    float se = ez;
    for (int o = 16; o; o >>= 1) se += __shfl_xor_sync(0xffffffffu, se, o);
    if (lane < N_CLASSES) out[g * N_CLASSES + lane] = zv - zm - logf(se);
}

// ---------------- launcher: kernel launches ONLY --------------------------
extern "C" void kernel_launch(void* const* d_in, const int* in_sizes, int n_in,
                              void* d_out, int out_size) {
    (void)in_sizes; (void)n_in; (void)out_size;
    const float* x     = (const float*)d_in[0];
    const void*  ei    = d_in[1];
    const void*  batch = d_in[2];
    const float* Wl    = (const float*)d_in[3];
    const float* Wr    = (const float*)d_in[4];
    const float* bl    = (const float*)d_in[5];
    const float* br    = (const float*)d_in[6];
    const float* att   = (const float*)d_in[7];
    const float* bias  = (const float*)d_in[8];
    const float* lin_w = (const float*)d_in[9];
    const float* lin_b = (const float*)d_in[10];
    float* out = (float*)d_out;

    // index dtype detection + CSR by destination (layer-invariant)
    k_detect    <<<1, 32>>>(ei);
    k_zero_deg  <<<(N_NODES + 255) / 256, 256>>>();
    k_count     <<<(E_TOT   + 255) / 256, 256>>>(ei);
    int nb = (N_NODES + 1023) / 1024;
    k_scan_block<<<nb, 1024>>>();
    k_scan_sums <<<1, 1>>>(nb);
    k_scan_final<<<(N_NODES + 255) / 256, 256>>>();
    k_scatter   <<<(E_TOT   + 255) / 256, 256>>>(ei);

    const int gemm_grid = (N_NODES + 63) / 64;
    const int attn_grid = (N_NODES * 32 + 255) / 256;
    for (int l = 0; l < N_LAYERS; l++) {
        int use_x = (l == 0) ? 1 : 0;
        k_gemm_tc<<<gemm_grid, 256>>>(x, use_x, Wl + l * 128 * 128, bl + l * 128, 0);
        k_gemm_tc<<<gemm_grid, 256>>>(x, use_x, Wr + l * 128 * 128, br + l * 128, 1);
        k_attn<<<attn_grid, 256>>>(att + l * 128, bias + l * 128);
    }

    k_zero_pool<<<(N_GRAPHS * HID + 255) / 256, 256>>>();
    k_pool     <<<(N_NODES * HID + 255) / 256, 256>>>(batch);
    k_final    <<<N_GRAPHS, 32>>>(lin_w, lin_b, out);
}

// round 15
// speedup vs baseline: 1.6582x; 1.0364x over previous
#include <cuda_runtime.h>
#include <math.h>
#include <stdint.h>

#define N_NODES   50000
#define N_EDGES   800000
#define E_TOT     (N_EDGES + N_NODES)   // 850000 (with self loops)
#define N_GRAPHS  64
#define HID       128
#define HEADS     4
#define CH        32
#define N_CLASSES 10
#define N_LAYERS  3
#define NEG_SLOPE 0.2f

// ---------------- scratch (module-load allocated, allowed) ----------------
__device__ __align__(16) float g_xl[N_NODES * HID];
__device__ __align__(16) float g_xr[N_NODES * HID];
__device__ __align__(16) float g_h [N_NODES * HID];
__device__ int   g_deg   [N_NODES];
__device__ int   g_incl  [N_NODES];
__device__ int   g_rowptr[N_NODES + 1];
__device__ int   g_cursor[N_NODES];
__device__ int   g_srcs  [E_TOT];
__device__ int   g_bsums[64];
__device__ int   g_boffs[64];
__device__ int   g_is64;
__device__ __align__(16) float g_pool[N_GRAPHS * HID];
__device__ float g_cnt [N_GRAPHS];

// dtype-robust index load (edge_index / batch may be int32 or int64)
__device__ __forceinline__ int load_idx(const void* p, long i, int is64) {
    if (is64) return (int)((const long long*)p)[i];
    return ((const int*)p)[i];
}

// ---------------- dtype detection -----------------------------------------
__global__ void k_detect(const void* __restrict__ ei) {
    if (threadIdx.x == 0 && blockIdx.x == 0) {
        const long long* p = (const long long*)ei;
        int ok = 1;
        for (int i = 0; i < 256; i++) {
            long long v = p[i];
            if (v < 0 || v >= N_NODES) { ok = 0; break; }
        }
        g_is64 = ok;
    }
}

// ---------------- CSR build (dst is layer-invariant; built once/launch) ---
__global__ void k_zero_deg() {
    int i = blockIdx.x * blockDim.x + threadIdx.x;
    if (i < N_NODES) g_deg[i] = 0;
}

__global__ void k_count(const void* __restrict__ ei) {
    int i = blockIdx.x * blockDim.x + threadIdx.x;
    int is64 = g_is64;
    if (i < E_TOT) {
        int dst = (i < N_EDGES) ? load_idx(ei, (long)N_EDGES + i, is64)
                                : (i - N_EDGES);
        if (dst >= 0 && dst < N_NODES) atomicAdd(&g_deg[dst], 1);
    }
}

__global__ void k_scan_block() {   // 49 blocks x 1024, Hillis-Steele
    __shared__ int s[1024];
    int i = blockIdx.x * 1024 + threadIdx.x;
    int v = (i < N_NODES) ? g_deg[i] : 0;
    s[threadIdx.x] = v;
    __syncthreads();
    for (int off = 1; off < 1024; off <<= 1) {
        int t = 0;
        if (threadIdx.x >= off) t = s[threadIdx.x - off];
        __syncthreads();
        if (threadIdx.x >= off) s[threadIdx.x] += t;
        __syncthreads();
    }
    if (i < N_NODES) g_incl[i] = s[threadIdx.x];
    if (threadIdx.x == 1023) g_bsums[blockIdx.x] = s[1023];
}

__global__ void k_scan_sums(int nb) {
    if (blockIdx.x == 0 && threadIdx.x == 0) {
        int acc = 0;
        for (int b = 0; b < nb; b++) { g_boffs[b] = acc; acc += g_bsums[b]; }
    }
}

__global__ void k_scan_final() {
    int i = blockIdx.x * blockDim.x + threadIdx.x;
    if (i < N_NODES) {
        int rp = g_incl[i] - g_deg[i] + g_boffs[i >> 10];
        g_rowptr[i] = rp;
        g_cursor[i] = rp;
    }
    if (i == 0) g_rowptr[N_NODES] = E_TOT;
}

__global__ void k_scatter(const void* __restrict__ ei) {
    int i = blockIdx.x * blockDim.x + threadIdx.x;
    int is64 = g_is64;
    if (i < E_TOT) {
        int src, dst;
        if (i < N_EDGES) {
            src = load_idx(ei, i, is64);
            dst = load_idx(ei, (long)N_EDGES + i, is64);
        } else {
            src = dst = i - N_EDGES;
        }
        if (src >= 0 && src < N_NODES && dst >= 0 && dst < N_NODES) {
            int pos = atomicAdd(&g_cursor[dst], 1);
            g_srcs[pos] = src;
        }
    }
}

// ---------------- TF32 split helper + MMA ---------------------------------
__device__ __forceinline__ void split_tf32(float v, uint32_t& hi, uint32_t& lo) {
    uint32_t h;
    asm("cvt.rna.tf32.f32 %0, %1;" : "=r"(h) : "f"(v));
    float r = v - __uint_as_float(h);
    uint32_t l;
    asm("cvt.rna.tf32.f32 %0, %1;" : "=r"(l) : "f"(v - __uint_as_float(h)));
    (void)r;
    hi = h; lo = l;
}

#define MMA_TF32(c, a, b0, b1)                                              \
    asm volatile(                                                           \
        "mma.sync.aligned.m16n8k8.row.col.f32.tf32.tf32.f32 "               \
        "{%0,%1,%2,%3}, {%4,%5,%6,%7}, {%8,%9}, {%0,%1,%2,%3};"             \
        : "+f"((c)[0]), "+f"((c)[1]), "+f"((c)[2]), "+f"((c)[3])            \
        : "r"((a)[0]), "r"((a)[1]), "r"((a)[2]), "r"((a)[3]),               \
          "r"(b0), "r"(b1))

// ------- fused dual GEMM (tensor core, 3xTF32) ----------------------------
// Computes xl = hin@Wl + bl AND xr = hin@Wr + br in one pass: A is staged
// and hi/lo-split ONCE (the split ALU work dominated the old per-W GEMMs).
// 256 thr = 8 warps (2x4). Warp tile 32x32 per output, m16n8k8.
__global__ __launch_bounds__(256, 2)
void k_gemm2_tc(const float* __restrict__ x_in, int use_x,
                const float* __restrict__ Wl, const float* __restrict__ Wr,
                const float* __restrict__ bl, const float* __restrict__ br) {
    const float* __restrict__ hin = use_x ? x_in : g_h;

    __shared__ float As_hi[64][20], As_lo[64][20];        // 64 rows x 16 k
    __shared__ float Ws_hi[2][16][136], Ws_lo[2][16][136];// [w][k][n]

    int tid  = threadIdx.x;
    int lane = tid & 31, wid = tid >> 5;
    int g = lane >> 2, t = lane & 3;
    int wm = wid >> 2, wn = wid & 3;
    int row0 = blockIdx.x * 64;

    float acc[2][2][4][4];   // [w][mt][nt][i]
#pragma unroll
    for (int w = 0; w < 2; w++)
#pragma unroll
        for (int mt = 0; mt < 2; mt++)
#pragma unroll
            for (int nt = 0; nt < 4; nt++)
#pragma unroll
                for (int i = 0; i < 4; i++) acc[w][mt][nt][i] = 0.f;

    for (int kc = 0; kc < 128; kc += 16) {
        // stage A 64x16 (1 float4 per thread) — split done once per chunk
        {
            int row = tid >> 2, k4 = (tid & 3) * 4;
            int grow = row0 + row;
            float4 v = make_float4(0.f, 0.f, 0.f, 0.f);
            if (grow < N_NODES) v = *(const float4*)&hin[grow * 128 + kc + k4];
            uint32_t h0, l0, h1, l1, h2, l2, h3, l3;
            split_tf32(v.x, h0, l0); split_tf32(v.y, h1, l1);
            split_tf32(v.z, h2, l2); split_tf32(v.w, h3, l3);
            float4 hh, ll;
            hh.x = __uint_as_float(h0); hh.y = __uint_as_float(h1);
            hh.z = __uint_as_float(h2); hh.w = __uint_as_float(h3);
            ll.x = __uint_as_float(l0); ll.y = __uint_as_float(l1);
            ll.z = __uint_as_float(l2); ll.w = __uint_as_float(l3);
            *(float4*)&As_hi[row][k4] = hh;
            *(float4*)&As_lo[row][k4] = ll;
        }
        // stage BOTH W tiles 2 x 16x128 (4 float4 per thread)
#pragma unroll
        for (int j = 0; j < 4; j++) {
            int f4 = tid + j * 256;               // 0..1023
            int w  = f4 >> 9;                     // 0: Wl, 1: Wr
            int rem = f4 & 511;
            int k = rem >> 5, n4 = (rem & 31) * 4;
            const float* Wp = w ? Wr : Wl;
            float4 v = *(const float4*)&Wp[(kc + k) * 128 + n4];
            uint32_t h0, l0, h1, l1, h2, l2, h3, l3;
            split_tf32(v.x, h0, l0); split_tf32(v.y, h1, l1);
            split_tf32(v.z, h2, l2); split_tf32(v.w, h3, l3);
            float4 hh, ll;
            hh.x = __uint_as_float(h0); hh.y = __uint_as_float(h1);
            hh.z = __uint_as_float(h2); hh.w = __uint_as_float(h3);
            ll.x = __uint_as_float(l0); ll.y = __uint_as_float(l1);
            ll.z = __uint_as_float(l2); ll.w = __uint_as_float(l3);
            *(float4*)&Ws_hi[w][k][n4] = hh;
            *(float4*)&Ws_lo[w][k][n4] = ll;
        }
        __syncthreads();

#pragma unroll
        for (int ks = 0; ks < 2; ks++) {
            int k0 = ks * 8;
            uint32_t ah[2][4], al[2][4];
#pragma unroll
            for (int mt = 0; mt < 2; mt++) {
                int rb = wm * 32 + mt * 16;
                ah[mt][0] = __float_as_uint(As_hi[rb + g    ][k0 + t    ]);
                ah[mt][1] = __float_as_uint(As_hi[rb + g + 8][k0 + t    ]);
                ah[mt][2] = __float_as_uint(As_hi[rb + g    ][k0 + t + 4]);
                ah[mt][3] = __float_as_uint(As_hi[rb + g + 8][k0 + t + 4]);
                al[mt][0] = __float_as_uint(As_lo[rb + g    ][k0 + t    ]);
                al[mt][1] = __float_as_uint(As_lo[rb + g + 8][k0 + t    ]);
                al[mt][2] = __float_as_uint(As_lo[rb + g    ][k0 + t + 4]);
                al[mt][3] = __float_as_uint(As_lo[rb + g + 8][k0 + t + 4]);
            }
#pragma unroll
            for (int w = 0; w < 2; w++) {
#pragma unroll
                for (int nt = 0; nt < 4; nt++) {
                    int col = wn * 32 + nt * 8 + g;
                    uint32_t bh0 = __float_as_uint(Ws_hi[w][k0 + t    ][col]);
                    uint32_t bh1 = __float_as_uint(Ws_hi[w][k0 + t + 4][col]);
                    uint32_t bl0 = __float_as_uint(Ws_lo[w][k0 + t    ][col]);
                    uint32_t bl1 = __float_as_uint(Ws_lo[w][k0 + t + 4][col]);
#pragma unroll
                    for (int mt = 0; mt < 2; mt++) {
                        MMA_TF32(acc[w][mt][nt], ah[mt], bh0, bh1);
                        MMA_TF32(acc[w][mt][nt], ah[mt], bl0, bl1);
                        MMA_TF32(acc[w][mt][nt], al[mt], bh0, bh1);
                    }
                }
            }
        }
        __syncthreads();
    }

    // epilogue: c0,c1 -> row g, cols 2t,2t+1 ; c2,c3 -> row g+8
#pragma unroll
    for (int w = 0; w < 2; w++) {
        float* __restrict__ out = w ? g_xr : g_xl;
        const float* __restrict__ bp = w ? br : bl;
#pragma unroll
        for (int mt = 0; mt < 2; mt++) {
            int r0 = row0 + wm * 32 + mt * 16 + g;
            int r1 = r0 + 8;
#pragma unroll
            for (int nt = 0; nt < 4; nt++) {
                int c = wn * 32 + nt * 8 + 2 * t;
                float2 bb = *(const float2*)&bp[c];
                if (r0 < N_NODES) {
                    float2 o;
                    o.x = acc[w][mt][nt][0] + bb.x;
                    o.y = acc[w][mt][nt][1] + bb.y;
                    *(float2*)&out[r0 * 128 + c] = o;
                }
                if (r1 < N_NODES) {
                    float2 o;
                    o.x = acc[w][mt][nt][2] + bb.x;
                    o.y = acc[w][mt][nt][3] + bb.y;
                    *(float2*)&out[r1 * 128 + c] = o;
                }
            }
        }
    }
}

// ------- fused GATv2 edge phase: one warp per dst, ONLINE softmax ---------
// Single sweep over the neighbor list (flash-attention style rescaling).
// 2-way unrolled so consecutive xl-row loads are in flight together.
__global__ __launch_bounds__(256)
void k_attn(const float* __restrict__ att_l, const float* __restrict__ bias_l) {
    int warp = (blockIdx.x * blockDim.x + threadIdx.x) >> 5;
    if (warp >= N_NODES) return;
    int lane = threadIdx.x & 31;
    int d = warp;
    int off = (lane >> 3) * 32 + (lane & 7) * 4;

    float4 xr4 = *(const float4*)&g_xr[d * 128 + off];
    float4 a4  = *(const float4*)&att_l[off];
    int beg = g_rowptr[d], end = g_rowptr[d + 1];

    float m = -1e30f, denom = 0.f;
    float ax = 0.f, ay = 0.f, az = 0.f, aw = 0.f;

    int j = beg;
    for (; j + 1 < end; j += 2) {
        int s0 = g_srcs[j], s1 = g_srcs[j + 1];
        float4 x0 = __ldg((const float4*)&g_xl[s0 * 128 + off]);
        float4 x1 = __ldg((const float4*)&g_xl[s1 * 128 + off]);

        float t0 = x0.x + xr4.x; t0 = t0 > 0.f ? t0 : NEG_SLOPE * t0;
        float t1 = x0.y + xr4.y; t1 = t1 > 0.f ? t1 : NEG_SLOPE * t1;
        float t2 = x0.z + xr4.z; t2 = t2 > 0.f ? t2 : NEG_SLOPE * t2;
        float t3 = x0.w + xr4.w; t3 = t3 > 0.f ? t3 : NEG_SLOPE * t3;
        float p0 = a4.x * t0 + a4.y * t1 + a4.z * t2 + a4.w * t3;
        p0 += __shfl_xor_sync(0xffffffffu, p0, 1);
        p0 += __shfl_xor_sync(0xffffffffu, p0, 2);
        p0 += __shfl_xor_sync(0xffffffffu, p0, 4);

        float u0 = x1.x + xr4.x; u0 = u0 > 0.f ? u0 : NEG_SLOPE * u0;
        float u1 = x1.y + xr4.y; u1 = u1 > 0.f ? u1 : NEG_SLOPE * u1;
        float u2 = x1.z + xr4.z; u2 = u2 > 0.f ? u2 : NEG_SLOPE * u2;
        float u3 = x1.w + xr4.w; u3 = u3 > 0.f ? u3 : NEG_SLOPE * u3;
        float p1 = a4.x * u0 + a4.y * u1 + a4.z * u2 + a4.w * u3;
        p1 += __shfl_xor_sync(0xffffffffu, p1, 1);
        p1 += __shfl_xor_sync(0xffffffffu, p1, 2);
        p1 += __shfl_xor_sync(0xffffffffu, p1, 4);

        // joint rescale for the pair
        float pm = fmaxf(p0, p1);
        float nm = fmaxf(m, pm);
        float scale = __expf(m - nm);
        float e0 = __expf(p0 - nm);
        float e1 = __expf(p1 - nm);
        denom = denom * scale + e0 + e1;
        ax = ax * scale + e0 * x0.x + e1 * x1.x;
        ay = ay * scale + e0 * x0.y + e1 * x1.y;
        az = az * scale + e0 * x0.z + e1 * x1.z;
        aw = aw * scale + e0 * x0.w + e1 * x1.w;
        m = nm;
    }
    if (j < end) {
        int s = g_srcs[j];
        float4 xs = __ldg((const float4*)&g_xl[s * 128 + off]);
        float t0 = xs.x + xr4.x; t0 = t0 > 0.f ? t0 : NEG_SLOPE * t0;
        float t1 = xs.y + xr4.y; t1 = t1 > 0.f ? t1 : NEG_SLOPE * t1;
        float t2 = xs.z + xr4.z; t2 = t2 > 0.f ? t2 : NEG_SLOPE * t2;
        float t3 = xs.w + xr4.w; t3 = t3 > 0.f ? t3 : NEG_SLOPE * t3;
        float p = a4.x * t0 + a4.y * t1 + a4.z * t2 + a4.w * t3;
        p += __shfl_xor_sync(0xffffffffu, p, 1);
        p += __shfl_xor_sync(0xffffffffu, p, 2);
        p += __shfl_xor_sync(0xffffffffu, p, 4);
        float nm = fmaxf(m, p);
        float scale = __expf(m - nm);
        float ee = __expf(p - nm);
        denom = denom * scale + ee;
        ax = ax * scale + ee * xs.x;
        ay = ay * scale + ee * xs.y;
        az = az * scale + ee * xs.z;
        aw = aw * scale + ee * xs.w;
        m = nm;
    }

    float inv = 1.f / denom;
    float4 bb = *(const float4*)&bias_l[off];
    float o0 = ax * inv + bb.x; o0 = o0 > 0.f ? o0 : expm1f(o0);
    float o1 = ay * inv + bb.y; o1 = o1 > 0.f ? o1 : expm1f(o1);
    float o2 = az * inv + bb.z; o2 = o2 > 0.f ? o2 : expm1f(o2);
    float o3 = aw * inv + bb.w; o3 = o3 > 0.f ? o3 : expm1f(o3);
    float4 o; o.x = o0; o.y = o1; o.z = o2; o.w = o3;
    *(float4*)&g_h[d * 128 + off] = o;
}

// ---------------- pooling + classifier head -------------------------------
__global__ void k_zero_pool() {
    int i = blockIdx.x * blockDim.x + threadIdx.x;
    if (i < N_GRAPHS * HID) g_pool[i] = 0.f;
    if (i < N_GRAPHS) g_cnt[i] = 0.f;
}

__global__ void k_pool(const void* __restrict__ batch) {
    int idx = blockIdx.x * blockDim.x + threadIdx.x;
    int is64 = g_is64;
    if (idx < N_NODES * HID) {
        int n = idx >> 7, c = idx & 127;
        int b = load_idx(batch, n, is64);
        if (b >= 0 && b < N_GRAPHS) {
            atomicAdd(&g_pool[b * 128 + c], g_h[idx]);
            if (c == 0) atomicAdd(&g_cnt[b], 1.f);
        }
    }
}

__global__ void k_final(const float* __restrict__ lin_w,
                        const float* __restrict__ lin_b,
                        float* __restrict__ out) {
    int g = blockIdx.x;
    int lane = threadIdx.x;          // 32 threads/block
    float z = -1e30f, zv = 0.f;
    if (lane < N_CLASSES) {
        float invc = 1.f / fmaxf(g_cnt[g], 1.f);
        float acc = lin_b[lane];
        for (int k = 0; k < 128; k++)
            acc += g_pool[g * 128 + k] * invc * lin_w[k * N_CLASSES + lane];
        acc = acc > 0.f ? acc : expm1f(acc);   // elu
        zv = acc; z = acc;
    }
    float zm = z;
    for (int o = 16; o; o >>= 1) zm = fmaxf(zm, __shfl_xor_sync(0xffffffffu, zm, o));
    float ez = (lane < N_CLASSES) ? __expf(zv - zm) : 0.f;
    float se = ez;
    for (int o = 16; o; o >>= 1) se += __shfl_xor_sync(0xffffffffu, se, o);
    if (lane < N_CLASSES) out[g * N_CLASSES + lane] = zv - zm - logf(se);
}

// ---------------- launcher: kernel launches ONLY --------------------------
extern "C" void kernel_launch(void* const* d_in, const int* in_sizes, int n_in,
                              void* d_out, int out_size) {
    (void)in_sizes; (void)n_in; (void)out_size;
    const float* x     = (const float*)d_in[0];
    const void*  ei    = d_in[1];
    const void*  batch = d_in[2];
    const float* Wl    = (const float*)d_in[3];
    const float* Wr    = (const float*)d_in[4];
    const float* bl    = (const float*)d_in[5];
    const float* br    = (const float*)d_in[6];
    const float* att   = (const float*)d_in[7];
    const float* bias  = (const float*)d_in[8];
    const float* lin_w = (const float*)d_in[9];
    const float* lin_b = (const float*)d_in[10];
    float* out = (float*)d_out;

    // index dtype detection + CSR by destination (layer-invariant)
    k_detect    <<<1, 32>>>(ei);
    k_zero_deg  <<<(N_NODES + 255) / 256, 256>>>();
    k_count     <<<(E_TOT   + 255) / 256, 256>>>(ei);
    int nb = (N_NODES + 1023) / 1024;
    k_scan_block<<<nb, 1024>>>();
    k_scan_sums <<<1, 1>>>(nb);
    k_scan_final<<<(N_NODES + 255) / 256, 256>>>();
    k_scatter   <<<(E_TOT   + 255) / 256, 256>>>(ei);

    const int gemm_grid = (N_NODES + 63) / 64;
    const int attn_grid = (N_NODES * 32 + 255) / 256;
    for (int l = 0; l < N_LAYERS; l++) {
        int use_x = (l == 0) ? 1 : 0;
        k_gemm2_tc<<<gemm_grid, 256>>>(x, use_x,
                                       Wl + l * 128 * 128, Wr + l * 128 * 128,
                                       bl + l * 128, br + l * 128);
        k_attn<<<attn_grid, 256>>>(att + l * 128, bias + l * 128);
    }

    k_zero_pool<<<(N_GRAPHS * HID + 255) / 256, 256>>>();
    k_pool     <<<(N_NODES * HID + 255) / 256, 256>>>(batch);
    k_final    <<<N_GRAPHS, 32>>>(lin_w, lin_b, out);
}

// round 16
// speedup vs baseline: 1.8185x; 1.0967x over previous
#include <cuda_runtime.h>
#include <math.h>
#include <stdint.h>

#define N_NODES   50000
#define N_EDGES   800000
#define E_TOT     (N_EDGES + N_NODES)   // 850000 (with self loops)
#define N_GRAPHS  64
#define HID       128
#define HEADS     4
#define CH        32
#define N_CLASSES 10
#define N_LAYERS  3
#define NEG_SLOPE 0.2f

// ---------------- scratch (module-load allocated, allowed) ----------------
__device__ __align__(16) float g_xl[N_NODES * HID];
__device__ __align__(16) float g_xr[N_NODES * HID];
__device__ __align__(16) float g_h [N_NODES * HID];
__device__ int   g_deg   [N_NODES];
__device__ int   g_incl  [N_NODES];
__device__ int   g_rowptr[N_NODES + 1];
__device__ int   g_cursor[N_NODES];
__device__ int   g_srcs  [E_TOT];
__device__ int   g_bsums[64];
__device__ int   g_boffs[64];
__device__ int   g_is64;
__device__ __align__(16) float g_pool[N_GRAPHS * HID];
__device__ float g_cnt [N_GRAPHS];

// dtype-robust index load (edge_index / batch may be int32 or int64)
__device__ __forceinline__ int load_idx(const void* p, long i, int is64) {
    if (is64) return (int)((const long long*)p)[i];
    return ((const int*)p)[i];
}

// ------------- dtype detection + zero degrees (merged) --------------------
__global__ void k_init(const void* __restrict__ ei) {
    int i = blockIdx.x * blockDim.x + threadIdx.x;
    if (i < N_NODES) g_deg[i] = 0;
    if (i == 0) {
        const long long* p = (const long long*)ei;
        int ok = 1;
        for (int k = 0; k < 256; k++) {
            long long v = p[k];
            if (v < 0 || v >= N_NODES) { ok = 0; break; }
        }
        g_is64 = ok;
    }
}

// ---------------- CSR build (dst is layer-invariant; built once/launch) ---
__global__ void k_count(const void* __restrict__ ei) {
    int i = blockIdx.x * blockDim.x + threadIdx.x;
    int is64 = g_is64;
    if (i < E_TOT) {
        int dst = (i < N_EDGES) ? load_idx(ei, (long)N_EDGES + i, is64)
                                : (i - N_EDGES);
        if (dst >= 0 && dst < N_NODES) atomicAdd(&g_deg[dst], 1);
    }
}

__global__ void k_scan_block() {   // 49 blocks x 1024, Hillis-Steele
    __shared__ int s[1024];
    int i = blockIdx.x * 1024 + threadIdx.x;
    int v = (i < N_NODES) ? g_deg[i] : 0;
    s[threadIdx.x] = v;
    __syncthreads();
    for (int off = 1; off < 1024; off <<= 1) {
        int t = 0;
        if (threadIdx.x >= off) t = s[threadIdx.x - off];
        __syncthreads();
        if (threadIdx.x >= off) s[threadIdx.x] += t;
        __syncthreads();
    }
    if (i < N_NODES) g_incl[i] = s[threadIdx.x];
    if (threadIdx.x == 1023) g_bsums[blockIdx.x] = s[1023];
}

__global__ void k_scan_sums(int nb) {
    if (blockIdx.x == 0 && threadIdx.x == 0) {
        int acc = 0;
        for (int b = 0; b < nb; b++) { g_boffs[b] = acc; acc += g_bsums[b]; }
    }
}

__global__ void k_scan_final() {
    int i = blockIdx.x * blockDim.x + threadIdx.x;
    if (i < N_NODES) {
        int rp = g_incl[i] - g_deg[i] + g_boffs[i >> 10];
        g_rowptr[i] = rp;
        g_cursor[i] = rp;
    }
    if (i == 0) g_rowptr[N_NODES] = E_TOT;
}

__global__ void k_scatter(const void* __restrict__ ei) {
    int i = blockIdx.x * blockDim.x + threadIdx.x;
    int is64 = g_is64;
    if (i < E_TOT) {
        int src, dst;
        if (i < N_EDGES) {
            src = load_idx(ei, i, is64);
            dst = load_idx(ei, (long)N_EDGES + i, is64);
        } else {
            src = dst = i - N_EDGES;
        }
        if (src >= 0 && src < N_NODES && dst >= 0 && dst < N_NODES) {
            int pos = atomicAdd(&g_cursor[dst], 1);
            g_srcs[pos] = src;
        }
    }
}

// ---------------- TF32 split helper + MMA ---------------------------------
__device__ __forceinline__ void split_tf32(float v, uint32_t& hi, uint32_t& lo) {
    uint32_t h;
    asm("cvt.rna.tf32.f32 %0, %1;" : "=r"(h) : "f"(v));
    uint32_t l;
    asm("cvt.rna.tf32.f32 %0, %1;" : "=r"(l) : "f"(v - __uint_as_float(h)));
    hi = h; lo = l;
}

#define MMA_TF32(c, a, b0, b1)                                              \
    asm volatile(                                                           \
        "mma.sync.aligned.m16n8k8.row.col.f32.tf32.tf32.f32 "               \
        "{%0,%1,%2,%3}, {%4,%5,%6,%7}, {%8,%9}, {%0,%1,%2,%3};"             \
        : "+f"((c)[0]), "+f"((c)[1]), "+f"((c)[2]), "+f"((c)[3])            \
        : "r"((a)[0]), "r"((a)[1]), "r"((a)[2]), "r"((a)[3]),               \
          "r"(b0), "r"(b1))

// ------- fused dual GEMM (tensor core, 3xTF32) ----------------------------
// xl = hin@Wl + bl AND xr = hin@Wr + br in one pass; A staged/split once.
__global__ __launch_bounds__(256, 2)
void k_gemm2_tc(const float* __restrict__ x_in, int use_x,
                const float* __restrict__ Wl, const float* __restrict__ Wr,
                const float* __restrict__ bl, const float* __restrict__ br) {
    const float* __restrict__ hin = use_x ? x_in : g_h;

    __shared__ float As_hi[64][20], As_lo[64][20];        // 64 rows x 16 k
    __shared__ float Ws_hi[2][16][136], Ws_lo[2][16][136];// [w][k][n]

    int tid  = threadIdx.x;
    int lane = tid & 31, wid = tid >> 5;
    int g = lane >> 2, t = lane & 3;
    int wm = wid >> 2, wn = wid & 3;
    int row0 = blockIdx.x * 64;

    float acc[2][2][4][4];   // [w][mt][nt][i]
#pragma unroll
    for (int w = 0; w < 2; w++)
#pragma unroll
        for (int mt = 0; mt < 2; mt++)
#pragma unroll
            for (int nt = 0; nt < 4; nt++)
#pragma unroll
                for (int i = 0; i < 4; i++) acc[w][mt][nt][i] = 0.f;

    for (int kc = 0; kc < 128; kc += 16) {
        // stage A 64x16 (1 float4 per thread) — split done once per chunk
        {
            int row = tid >> 2, k4 = (tid & 3) * 4;
            int grow = row0 + row;
            float4 v = make_float4(0.f, 0.f, 0.f, 0.f);
            if (grow < N_NODES) v = *(const float4*)&hin[grow * 128 + kc + k4];
            uint32_t h0, l0, h1, l1, h2, l2, h3, l3;
            split_tf32(v.x, h0, l0); split_tf32(v.y, h1, l1);
            split_tf32(v.z, h2, l2); split_tf32(v.w, h3, l3);
            float4 hh, ll;
            hh.x = __uint_as_float(h0); hh.y = __uint_as_float(h1);
            hh.z = __uint_as_float(h2); hh.w = __uint_as_float(h3);
            ll.x = __uint_as_float(l0); ll.y = __uint_as_float(l1);
            ll.z = __uint_as_float(l2); ll.w = __uint_as_float(l3);
            *(float4*)&As_hi[row][k4] = hh;
            *(float4*)&As_lo[row][k4] = ll;
        }
        // stage BOTH W tiles 2 x 16x128 (4 float4 per thread)
#pragma unroll
        for (int j = 0; j < 4; j++) {
            int f4 = tid + j * 256;               // 0..1023
            int w  = f4 >> 9;                     // 0: Wl, 1: Wr
            int rem = f4 & 511;
            int k = rem >> 5, n4 = (rem & 31) * 4;
            const float* Wp = w ? Wr : Wl;
            float4 v = *(const float4*)&Wp[(kc + k) * 128 + n4];
            uint32_t h0, l0, h1, l1, h2, l2, h3, l3;
            split_tf32(v.x, h0, l0); split_tf32(v.y, h1, l1);
            split_tf32(v.z, h2, l2); split_tf32(v.w, h3, l3);
            float4 hh, ll;
            hh.x = __uint_as_float(h0); hh.y = __uint_as_float(h1);
            hh.z = __uint_as_float(h2); hh.w = __uint_as_float(h3);
            ll.x = __uint_as_float(l0); ll.y = __uint_as_float(l1);
            ll.z = __uint_as_float(l2); ll.w = __uint_as_float(l3);
            *(float4*)&Ws_hi[w][k][n4] = hh;
            *(float4*)&Ws_lo[w][k][n4] = ll;
        }
        __syncthreads();

#pragma unroll
        for (int ks = 0; ks < 2; ks++) {
            int k0 = ks * 8;
            uint32_t ah[2][4], al[2][4];
#pragma unroll
            for (int mt = 0; mt < 2; mt++) {
                int rb = wm * 32 + mt * 16;
                ah[mt][0] = __float_as_uint(As_hi[rb + g    ][k0 + t    ]);
                ah[mt][1] = __float_as_uint(As_hi[rb + g + 8][k0 + t    ]);
                ah[mt][2] = __float_as_uint(As_hi[rb + g    ][k0 + t + 4]);
                ah[mt][3] = __float_as_uint(As_hi[rb + g + 8][k0 + t + 4]);
                al[mt][0] = __float_as_uint(As_lo[rb + g    ][k0 + t    ]);
                al[mt][1] = __float_as_uint(As_lo[rb + g + 8][k0 + t    ]);
                al[mt][2] = __float_as_uint(As_lo[rb + g    ][k0 + t + 4]);
                al[mt][3] = __float_as_uint(As_lo[rb + g + 8][k0 + t + 4]);
            }
#pragma unroll
            for (int w = 0; w < 2; w++) {
#pragma unroll
                for (int nt = 0; nt < 4; nt++) {
                    int col = wn * 32 + nt * 8 + g;
                    uint32_t bh0 = __float_as_uint(Ws_hi[w][k0 + t    ][col]);
                    uint32_t bh1 = __float_as_uint(Ws_hi[w][k0 + t + 4][col]);
                    uint32_t bl0 = __float_as_uint(Ws_lo[w][k0 + t    ][col]);
                    uint32_t bl1 = __float_as_uint(Ws_lo[w][k0 + t + 4][col]);
#pragma unroll
                    for (int mt = 0; mt < 2; mt++) {
                        MMA_TF32(acc[w][mt][nt], ah[mt], bh0, bh1);
                        MMA_TF32(acc[w][mt][nt], ah[mt], bl0, bl1);
                        MMA_TF32(acc[w][mt][nt], al[mt], bh0, bh1);
                    }
                }
            }
        }
        __syncthreads();
    }

    // epilogue: c0,c1 -> row g, cols 2t,2t+1 ; c2,c3 -> row g+8
#pragma unroll
    for (int w = 0; w < 2; w++) {
        float* __restrict__ out = w ? g_xr : g_xl;
        const float* __restrict__ bp = w ? br : bl;
#pragma unroll
        for (int mt = 0; mt < 2; mt++) {
            int r0 = row0 + wm * 32 + mt * 16 + g;
            int r1 = r0 + 8;
#pragma unroll
            for (int nt = 0; nt < 4; nt++) {
                int c = wn * 32 + nt * 8 + 2 * t;
                float2 bb = *(const float2*)&bp[c];
                if (r0 < N_NODES) {
                    float2 o;
                    o.x = acc[w][mt][nt][0] + bb.x;
                    o.y = acc[w][mt][nt][1] + bb.y;
                    *(float2*)&out[r0 * 128 + c] = o;
                }
                if (r1 < N_NODES) {
                    float2 o;
                    o.x = acc[w][mt][nt][2] + bb.x;
                    o.y = acc[w][mt][nt][3] + bb.y;
                    *(float2*)&out[r1 * 128 + c] = o;
                }
            }
        }
    }
}

// ------- fused GATv2 edge phase: one warp per dst, ONLINE softmax ---------
// Single sweep, 4-way unrolled (MLP 4 on the random xl-row loads).
__global__ __launch_bounds__(256)
void k_attn(const float* __restrict__ att_l, const float* __restrict__ bias_l) {
    int warp = (blockIdx.x * blockDim.x + threadIdx.x) >> 5;
    if (warp >= N_NODES) return;
    int lane = threadIdx.x & 31;
    int d = warp;
    int off = (lane >> 3) * 32 + (lane & 7) * 4;

    float4 xr4 = *(const float4*)&g_xr[d * 128 + off];
    float4 a4  = *(const float4*)&att_l[off];
    int beg = g_rowptr[d], end = g_rowptr[d + 1];

    float m = -1e30f, denom = 0.f;
    float ax = 0.f, ay = 0.f, az = 0.f, aw = 0.f;

    int j = beg;
    for (; j + 3 < end; j += 4) {
        int s0 = g_srcs[j],     s1 = g_srcs[j + 1];
        int s2 = g_srcs[j + 2], s3 = g_srcs[j + 3];
        float4 x0 = __ldg((const float4*)&g_xl[s0 * 128 + off]);
        float4 x1 = __ldg((const float4*)&g_xl[s1 * 128 + off]);
        float4 x2 = __ldg((const float4*)&g_xl[s2 * 128 + off]);
        float4 x3 = __ldg((const float4*)&g_xl[s3 * 128 + off]);

        float t0, t1, t2, t3;
        t0 = x0.x + xr4.x; t0 = t0 > 0.f ? t0 : NEG_SLOPE * t0;
        t1 = x0.y + xr4.y; t1 = t1 > 0.f ? t1 : NEG_SLOPE * t1;
        t2 = x0.z + xr4.z; t2 = t2 > 0.f ? t2 : NEG_SLOPE * t2;
        t3 = x0.w + xr4.w; t3 = t3 > 0.f ? t3 : NEG_SLOPE * t3;
        float p0 = a4.x * t0 + a4.y * t1 + a4.z * t2 + a4.w * t3;
        t0 = x1.x + xr4.x; t0 = t0 > 0.f ? t0 : NEG_SLOPE * t0;
        t1 = x1.y + xr4.y; t1 = t1 > 0.f ? t1 : NEG_SLOPE * t1;
        t2 = x1.z + xr4.z; t2 = t2 > 0.f ? t2 : NEG_SLOPE * t2;
        t3 = x1.w + xr4.w; t3 = t3 > 0.f ? t3 : NEG_SLOPE * t3;
        float p1 = a4.x * t0 + a4.y * t1 + a4.z * t2 + a4.w * t3;
        t0 = x2.x + xr4.x; t0 = t0 > 0.f ? t0 : NEG_SLOPE * t0;
        t1 = x2.y + xr4.y; t1 = t1 > 0.f ? t1 : NEG_SLOPE * t1;
        t2 = x2.z + xr4.z; t2 = t2 > 0.f ? t2 : NEG_SLOPE * t2;
        t3 = x2.w + xr4.w; t3 = t3 > 0.f ? t3 : NEG_SLOPE * t3;
        float p2 = a4.x * t0 + a4.y * t1 + a4.z * t2 + a4.w * t3;
        t0 = x3.x + xr4.x; t0 = t0 > 0.f ? t0 : NEG_SLOPE * t0;
        t1 = x3.y + xr4.y; t1 = t1 > 0.f ? t1 : NEG_SLOPE * t1;
        t2 = x3.z + xr4.z; t2 = t2 > 0.f ? t2 : NEG_SLOPE * t2;
        t3 = x3.w + xr4.w; t3 = t3 > 0.f ? t3 : NEG_SLOPE * t3;
        float p3 = a4.x * t0 + a4.y * t1 + a4.z * t2 + a4.w * t3;

        p0 += __shfl_xor_sync(0xffffffffu, p0, 1);
        p1 += __shfl_xor_sync(0xffffffffu, p1, 1);
        p2 += __shfl_xor_sync(0xffffffffu, p2, 1);
        p3 += __shfl_xor_sync(0xffffffffu, p3, 1);
        p0 += __shfl_xor_sync(0xffffffffu, p0, 2);
        p1 += __shfl_xor_sync(0xffffffffu, p1, 2);
        p2 += __shfl_xor_sync(0xffffffffu, p2, 2);
        p3 += __shfl_xor_sync(0xffffffffu, p3, 2);
        p0 += __shfl_xor_sync(0xffffffffu, p0, 4);
        p1 += __shfl_xor_sync(0xffffffffu, p1, 4);
        p2 += __shfl_xor_sync(0xffffffffu, p2, 4);
        p3 += __shfl_xor_sync(0xffffffffu, p3, 4);

        float pm = fmaxf(fmaxf(p0, p1), fmaxf(p2, p3));
        float nm = fmaxf(m, pm);
        float scale = __expf(m - nm);
        float e0 = __expf(p0 - nm);
        float e1 = __expf(p1 - nm);
        float e2 = __expf(p2 - nm);
        float e3 = __expf(p3 - nm);
        denom = denom * scale + (e0 + e1) + (e2 + e3);
        ax = ax * scale + e0 * x0.x + e1 * x1.x + e2 * x2.x + e3 * x3.x;
        ay = ay * scale + e0 * x0.y + e1 * x1.y + e2 * x2.y + e3 * x3.y;
        az = az * scale + e0 * x0.z + e1 * x1.z + e2 * x2.z + e3 * x3.z;
        aw = aw * scale + e0 * x0.w + e1 * x1.w + e2 * x2.w + e3 * x3.w;
        m = nm;
    }
    for (; j < end; j++) {
        int s = g_srcs[j];
        float4 xs = __ldg((const float4*)&g_xl[s * 128 + off]);
        float t0 = xs.x + xr4.x; t0 = t0 > 0.f ? t0 : NEG_SLOPE * t0;
        float t1 = xs.y + xr4.y; t1 = t1 > 0.f ? t1 : NEG_SLOPE * t1;
        float t2 = xs.z + xr4.z; t2 = t2 > 0.f ? t2 : NEG_SLOPE * t2;
        float t3 = xs.w + xr4.w; t3 = t3 > 0.f ? t3 : NEG_SLOPE * t3;
        float p = a4.x * t0 + a4.y * t1 + a4.z * t2 + a4.w * t3;
        p += __shfl_xor_sync(0xffffffffu, p, 1);
        p += __shfl_xor_sync(0xffffffffu, p, 2);
        p += __shfl_xor_sync(0xffffffffu, p, 4);
        float nm = fmaxf(m, p);
        float scale = __expf(m - nm);
        float ee = __expf(p - nm);
        denom = denom * scale + ee;
        ax = ax * scale + ee * xs.x;
        ay = ay * scale + ee * xs.y;
        az = az * scale + ee * xs.z;
        aw = aw * scale + ee * xs.w;
        m = nm;
    }

    float inv = 1.f / denom;
    float4 bb = *(const float4*)&bias_l[off];
    float o0 = ax * inv + bb.x; o0 = o0 > 0.f ? o0 : expm1f(o0);
    float o1 = ay * inv + bb.y; o1 = o1 > 0.f ? o1 : expm1f(o1);
    float o2 = az * inv + bb.z; o2 = o2 > 0.f ? o2 : expm1f(o2);
    float o3 = aw * inv + bb.w; o3 = o3 > 0.f ? o3 : expm1f(o3);
    float4 o; o.x = o0; o.y = o1; o.z = o2; o.w = o3;
    *(float4*)&g_h[d * 128 + off] = o;
}

// ----- pooling: batch is SORTED -> per-graph contiguous segment sum -------
// 64 blocks x 128 threads; block g binary-searches its node range, then each
// thread sums its column. No atomics, no zero-init kernel.
__global__ void k_pool_seg(const void* __restrict__ batch) {
    __shared__ int s_bounds[2];
    int g = blockIdx.x;
    int is64 = g_is64;
    if (threadIdx.x < 2) {
        int target = g + threadIdx.x;          // lower_bound(target)
        int lo = 0, hi = N_NODES;
        while (lo < hi) {
            int mid = (lo + hi) >> 1;
            if (load_idx(batch, mid, is64) < target) lo = mid + 1;
            else hi = mid;
        }
        s_bounds[threadIdx.x] = lo;
    }
    __syncthreads();
    int start = s_bounds[0], end = s_bounds[1];
    int c = threadIdx.x;                        // 128 cols
    float sum = 0.f;
    for (int n = start; n < end; n++) sum += g_h[n * 128 + c];
    g_pool[g * 128 + c] = sum;
    if (c == 0) g_cnt[g] = (float)(end - start);
}

__global__ void k_final(const float* __restrict__ lin_w,
                        const float* __restrict__ lin_b,
                        float* __restrict__ out) {
    int g = blockIdx.x;
    int lane = threadIdx.x;          // 32 threads/block
    float z = -1e30f, zv = 0.f;
    if (lane < N_CLASSES) {
        float invc = 1.f / fmaxf(g_cnt[g], 1.f);
        float acc = lin_b[lane];
        for (int k = 0; k < 128; k++)
            acc += g_pool[g * 128 + k] * invc * lin_w[k * N_CLASSES + lane];
        acc = acc > 0.f ? acc : expm1f(acc);   // elu
        zv = acc; z = acc;
    }
    float zm = z;
    for (int o = 16; o; o >>= 1) zm = fmaxf(zm, __shfl_xor_sync(0xffffffffu, zm, o));
    float ez = (lane < N_CLASSES) ? __expf(zv - zm) : 0.f;
    float se = ez;
    for (int o = 16; o; o >>= 1) se += __shfl_xor_sync(0xffffffffu, se, o);
    if (lane < N_CLASSES) out[g * N_CLASSES + lane] = zv - zm - logf(se);
}

// ---------------- launcher: kernel launches ONLY --------------------------
extern "C" void kernel_launch(void* const* d_in, const int* in_sizes, int n_in,
                              void* d_out, int out_size) {
    (void)in_sizes; (void)n_in; (void)out_size;
    const float* x     = (const float*)d_in[0];
    const void*  ei    = d_in[1];
    const void*  batch = d_in[2];
    const float* Wl    = (const float*)d_in[3];
    const float* Wr    = (const float*)d_in[4];
    const float* bl    = (const float*)d_in[5];
    const float* br    = (const float*)d_in[6];
    const float* att   = (const float*)d_in[7];
    const float* bias  = (const float*)d_in[8];
    const float* lin_w = (const float*)d_in[9];
    const float* lin_b = (const float*)d_in[10];
    float* out = (float*)d_out;

    // dtype detect + zero deg (merged), then CSR by destination
    k_init      <<<(N_NODES + 255) / 256, 256>>>(ei);
    k_count     <<<(E_TOT   + 255) / 256, 256>>>(ei);
    int nb = (N_NODES + 1023) / 1024;
    k_scan_block<<<nb, 1024>>>();
    k_scan_sums <<<1, 1>>>(nb);
    k_scan_final<<<(N_NODES + 255) / 256, 256>>>();
    k_scatter   <<<(E_TOT   + 255) / 256, 256>>>(ei);

    const int gemm_grid = (N_NODES + 63) / 64;
    const int attn_grid = (N_NODES * 32 + 255) / 256;
    for (int l = 0; l < N_LAYERS; l++) {
        int use_x = (l == 0) ? 1 : 0;
        k_gemm2_tc<<<gemm_grid, 256>>>(x, use_x,
                                       Wl + l * 128 * 128, Wr + l * 128 * 128,
                                       bl + l * 128, br + l * 128);
        k_attn<<<attn_grid, 256>>>(att + l * 128, bias + l * 128);
    }

    k_pool_seg<<<N_GRAPHS, 128>>>(batch);
    k_final   <<<N_GRAPHS, 32>>>(lin_w, lin_b, out);
}